// round 6
// baseline (speedup 1.0000x reference)
#include <cuda_runtime.h>
#include <cuda_bf16.h>
#include <math.h>
#include <stdint.h>

// Problem constants
#define BB 2
#define TT 2048
#define CC 2048
#define HH 16
#define KVH 4
#define DD 128
#define RR 4            // HH / KVH
#define HALF 64         // DD/2

// ---------------------------------------------------------------------------
// Scratch (device globals — allowed)
// ---------------------------------------------------------------------------
__device__ float g_q[(size_t)BB * TT * HH * DD];     // (B,T,H,D)
__device__ float g_k[(size_t)BB * TT * KVH * DD];    // (B,T,KV,D)
__device__ float g_v[(size_t)BB * TT * KVH * DD];    // (B,T,KV,D)
__device__ float g_attn[(size_t)BB * TT * CC];       // (B,T,C)

// ---------------------------------------------------------------------------
// Fast exp (FFMA-only; avoids MUFU bottleneck). Valid for x <= ~0, handles -inf.
// ---------------------------------------------------------------------------
__device__ __forceinline__ float fast_exp(float x) {
    float t = x * 1.4426950408889634f;          // log2(e)
    if (t < -126.0f) return 0.0f;               // also catches -inf / huge-neg mask
    float z = t + 12582912.0f;                  // 1.5 * 2^23
    float fi = z - 12582912.0f;
    float f = t - fi;                           // f in [-0.5, 0.5]
    int e = __float_as_int(z) - 0x4B400000;     // integer part
    float p = 1.535336188319500e-4f;
    p = fmaf(p, f, 1.339887440266574e-3f);
    p = fmaf(p, f, 9.618437357674640e-3f);
    p = fmaf(p, f, 5.550332471162809e-2f);
    p = fmaf(p, f, 2.402264791363012e-1f);
    p = fmaf(p, f, 6.931472028550421e-1f);
    p = fmaf(p, f, 1.0f);
    float scale = __int_as_float((e + 127) << 23);
    return p * scale;
}

// ---------------------------------------------------------------------------
// TF32 helpers
// ---------------------------------------------------------------------------
__device__ __forceinline__ uint32_t f2tf32(float x) {
    uint32_t r;
    asm volatile("cvt.rna.tf32.f32 %0, %1;" : "=r"(r) : "f"(x));
    return r;
}

__device__ __forceinline__ void mma_tf32(float* c, const uint32_t* a, const uint32_t* b) {
    asm volatile(
        "mma.sync.aligned.m16n8k8.row.col.f32.tf32.tf32.f32 "
        "{%0,%1,%2,%3}, {%4,%5,%6,%7}, {%8,%9}, {%0,%1,%2,%3};"
        : "+f"(c[0]), "+f"(c[1]), "+f"(c[2]), "+f"(c[3])
        : "r"(a[0]), "r"(a[1]), "r"(a[2]), "r"(a[3]), "r"(b[0]), "r"(b[1]));
}

// ---------------------------------------------------------------------------
// TF32 3-pass split GEMM: C = A(MxK) @ B(KxN), row-major, fp32-quality.
// BM=BN=128, BK=16, 256 threads = 8 warps (2x4), warp tile 64x32,
// per warp 4x4 mma tiles of m16n8k8. Requires M%128==0, N%128==0, K%16==0.
// ---------------------------------------------------------------------------
#define APAD 20     // A smem row stride (floats): conflict-free frag loads
#define BPAD 136    // B smem row stride (floats): conflict-free frag loads

__global__ void __launch_bounds__(256) tf32_gemm_kernel(
    const float* __restrict__ A, const float* __restrict__ B,
    float* __restrict__ C, int M, int N, int K)
{
    __shared__ float Ah[128][APAD];
    __shared__ float Al[128][APAD];
    __shared__ float Bh[16][BPAD];
    __shared__ float Bl[16][BPAD];

    const int tid  = threadIdx.x;
    const int warp = tid >> 5;
    const int lane = tid & 31;
    const int g    = lane >> 2;     // 0..7
    const int t    = lane & 3;      // 0..3
    const int wm   = (warp >> 2) * 64;   // {0, 64}
    const int wn   = (warp & 3) * 32;    // {0,32,64,96}
    const int row0 = blockIdx.y * 128;
    const int col0 = blockIdx.x * 128;

    float acc[4][4][4];
#pragma unroll
    for (int i = 0; i < 4; ++i)
#pragma unroll
        for (int j = 0; j < 4; ++j)
#pragma unroll
            for (int c = 0; c < 4; ++c) acc[i][j][c] = 0.0f;

    for (int k0 = 0; k0 < K; k0 += 16) {
        // Load + split A tile (128x16) and B tile (16x128)
#pragma unroll
        for (int ld = 0; ld < 2; ++ld) {
            int idx = tid + ld * 256;            // 0..511
            {
                int m  = idx >> 2;               // 0..127
                int kq = (idx & 3) << 2;         // 0,4,8,12
                float4 v = *(const float4*)&A[(size_t)(row0 + m) * K + k0 + kq];
                float vv[4] = {v.x, v.y, v.z, v.w};
#pragma unroll
                for (int j = 0; j < 4; ++j) {
                    float hf = __uint_as_float(f2tf32(vv[j]));
                    Ah[m][kq + j] = hf;
                    Al[m][kq + j] = __uint_as_float(f2tf32(vv[j] - hf));
                }
            }
            {
                int kk = idx >> 5;               // 0..15
                int nq = (idx & 31) << 2;        // 0..124
                float4 v = *(const float4*)&B[(size_t)(k0 + kk) * N + col0 + nq];
                float vv[4] = {v.x, v.y, v.z, v.w};
#pragma unroll
                for (int j = 0; j < 4; ++j) {
                    float hf = __uint_as_float(f2tf32(vv[j]));
                    Bh[kk][nq + j] = hf;
                    Bl[kk][nq + j] = __uint_as_float(f2tf32(vv[j] - hf));
                }
            }
        }
        __syncthreads();

#pragma unroll
        for (int ks = 0; ks < 16; ks += 8) {
            uint32_t bh[4][2], bl[4][2];
#pragma unroll
            for (int nt = 0; nt < 4; ++nt) {
                int col = wn + nt * 8 + g;
                bh[nt][0] = __float_as_uint(Bh[ks + t][col]);
                bh[nt][1] = __float_as_uint(Bh[ks + t + 4][col]);
                bl[nt][0] = __float_as_uint(Bl[ks + t][col]);
                bl[nt][1] = __float_as_uint(Bl[ks + t + 4][col]);
            }
#pragma unroll
            for (int mt = 0; mt < 4; ++mt) {
                int rm = wm + mt * 16;
                uint32_t ah[4], al[4];
                ah[0] = __float_as_uint(Ah[rm + g][ks + t]);
                ah[1] = __float_as_uint(Ah[rm + g + 8][ks + t]);
                ah[2] = __float_as_uint(Ah[rm + g][ks + t + 4]);
                ah[3] = __float_as_uint(Ah[rm + g + 8][ks + t + 4]);
                al[0] = __float_as_uint(Al[rm + g][ks + t]);
                al[1] = __float_as_uint(Al[rm + g + 8][ks + t]);
                al[2] = __float_as_uint(Al[rm + g][ks + t + 4]);
                al[3] = __float_as_uint(Al[rm + g + 8][ks + t + 4]);
#pragma unroll
                for (int nt = 0; nt < 4; ++nt) {
                    mma_tf32(acc[mt][nt], ah, bh[nt]);   // hi*hi
                    mma_tf32(acc[mt][nt], ah, bl[nt]);   // hi*lo
                    mma_tf32(acc[mt][nt], al, bh[nt]);   // lo*hi
                }
            }
        }
        __syncthreads();
    }

    // Epilogue: c0,c1 -> (row, 2t), (row, 2t+1); c2,c3 -> (row+8, ...)
#pragma unroll
    for (int mt = 0; mt < 4; ++mt) {
#pragma unroll
        for (int nt = 0; nt < 4; ++nt) {
            int row = row0 + wm + mt * 16 + g;
            int col = col0 + wn + nt * 8 + 2 * t;
            float2 v01 = make_float2(acc[mt][nt][0], acc[mt][nt][1]);
            float2 v23 = make_float2(acc[mt][nt][2], acc[mt][nt][3]);
            *(float2*)&C[(size_t)row * N + col]       = v01;
            *(float2*)&C[(size_t)(row + 8) * N + col] = v23;
        }
    }
}

// ---------------------------------------------------------------------------
// RoPE in-place over X: (B, T, NH, D). One thread per (b,t,h,freq) pair.
// ---------------------------------------------------------------------------
__global__ void rope_kernel(float* __restrict__ X, int NH, int total_pairs)
{
    int idx = blockIdx.x * blockDim.x + threadIdx.x;
    if (idx >= total_pairs) return;
    int i = idx & (HALF - 1);
    int h = (idx >> 6) % NH;
    int t = (idx / (HALF * NH)) % TT;
    int b = idx / (HALF * NH * TT);

    float theta = powf(10000.0f, -(float)i * (1.0f / (float)HALF));
    float ang = (float)t * theta;
    float s, c;
    sincosf(ang, &s, &c);

    size_t base = (((size_t)b * TT + t) * NH + h) * DD;
    float x1 = X[base + i];
    float x2 = X[base + i + HALF];
    X[base + i]        = x1 * c - x2 * s;
    X[base + i + HALF] = x2 * c + x1 * s;
}

// ---------------------------------------------------------------------------
// Flash attention fp32. BQ=BKV=64, D=128, 256 threads, dynamic smem.
// Q:(B,T,H,D)  K,V:(B,T,KV,D)  O:(B,T,C) with C index = h*D + d
// grid: (T/64, H, B)
// ---------------------------------------------------------------------------
#define QT_LD 68          // padded row length for transposed Q/K tiles (128x68)
#define SS_LD 65          // padded row length for score tile (64x65)
#define SM_QT 0
#define SM_KV (128 * QT_LD)
#define SM_SS (SM_KV + 128 * QT_LD)
#define SM_M  (SM_SS + 64 * SS_LD)
#define SM_L  (SM_M + 64)
#define SM_A  (SM_L + 64)
#define SM_TOTAL_FLOATS (SM_A + 64)
#define ATTN_SMEM_BYTES (SM_TOTAL_FLOATS * 4)

__global__ void __launch_bounds__(256) attn_kernel(
    const float* __restrict__ Q, const float* __restrict__ K,
    const float* __restrict__ V, float* __restrict__ O)
{
    extern __shared__ float sm[];
    float* QsT  = sm + SM_QT;   // [128][QT_LD]  (d-major)
    float* KVu  = sm + SM_KV;   // K phase: [128][QT_LD]; V phase: [64][128]
    float* Ss   = sm + SM_SS;   // [64][SS_LD]
    float* m_sm = sm + SM_M;
    float* l_sm = sm + SM_L;
    float* a_sm = sm + SM_A;

    const int tid   = threadIdx.x;
    const int qtile = blockIdx.x;
    const int h     = blockIdx.y;
    const int b     = blockIdx.z;
    const int g     = h >> 2;            // GQA kv head
    const int q0    = qtile * 64;

    for (int i = tid; i < 64 * 128; i += 256) {
        int r = i >> 7, d = i & 127;
        QsT[d * QT_LD + r] = Q[(size_t)(b * TT + q0 + r) * (HH * DD) + h * DD + d];
    }
    if (tid < 64) { m_sm[tid] = -1e30f; l_sm[tid] = 0.0f; }

    float o[4][8];
#pragma unroll
    for (int i = 0; i < 4; ++i)
#pragma unroll
        for (int j = 0; j < 8; ++j) o[i][j] = 0.0f;

    const int r0  = (tid >> 4) * 4;
    const int c0  = (tid & 15) * 4;
    const int c0p = (tid & 15) * 8;
    const int warp = tid >> 5, lane = tid & 31;
    __syncthreads();

    for (int t = 0; t <= qtile; ++t) {
        const int s0 = t * 64;

        for (int i = tid; i < 64 * 128; i += 256) {
            int r = i >> 7, d = i & 127;
            KVu[d * QT_LD + r] = K[(size_t)(b * TT + s0 + r) * (KVH * DD) + g * DD + d];
        }
        __syncthreads();

        float acc[4][4];
#pragma unroll
        for (int i = 0; i < 4; ++i)
#pragma unroll
            for (int j = 0; j < 4; ++j) acc[i][j] = 0.0f;

        for (int k = 0; k < 128; ++k) {
            float4 qv = *(const float4*)(QsT + k * QT_LD + r0);
            float4 kv = *(const float4*)(KVu + k * QT_LD + c0);
            float qa[4] = {qv.x, qv.y, qv.z, qv.w};
            float ka[4] = {kv.x, kv.y, kv.z, kv.w};
#pragma unroll
            for (int i = 0; i < 4; ++i)
#pragma unroll
                for (int j = 0; j < 4; ++j)
                    acc[i][j] = fmaf(qa[i], ka[j], acc[i][j]);
        }
        const float scale = 0.08838834764831843f;   // 1/sqrt(128)
#pragma unroll
        for (int i = 0; i < 4; ++i)
#pragma unroll
            for (int j = 0; j < 4; ++j) {
                float v = acc[i][j] * scale;
                if (s0 + c0 + j > q0 + r0 + i) v = -1e30f;
                Ss[(r0 + i) * SS_LD + c0 + j] = v;
            }
        __syncthreads();

        for (int r = warp; r < 64; r += 8) {
            float v0 = Ss[r * SS_LD + lane];
            float v1 = Ss[r * SS_LD + lane + 32];
            float mx = fmaxf(v0, v1);
#pragma unroll
            for (int off = 16; off > 0; off >>= 1)
                mx = fmaxf(mx, __shfl_xor_sync(0xffffffffu, mx, off));
            float m_old = m_sm[r];
            float m_new = fmaxf(m_old, mx);
            float p0 = fast_exp(v0 - m_new);
            float p1 = fast_exp(v1 - m_new);
            Ss[r * SS_LD + lane]      = p0;
            Ss[r * SS_LD + lane + 32] = p1;
            float s = p0 + p1;
#pragma unroll
            for (int off = 16; off > 0; off >>= 1)
                s += __shfl_xor_sync(0xffffffffu, s, off);
            if (lane == 0) {
                float a = fast_exp(m_old - m_new);
                a_sm[r] = a;
                l_sm[r] = l_sm[r] * a + s;
                m_sm[r] = m_new;
            }
        }

        for (int i = tid; i < 64 * 128; i += 256) {
            int r = i >> 7, d = i & 127;
            KVu[r * 128 + d] = V[(size_t)(b * TT + s0 + r) * (KVH * DD) + g * DD + d];
        }
        __syncthreads();

        float al[4];
#pragma unroll
        for (int i = 0; i < 4; ++i) {
            al[i] = a_sm[r0 + i];
#pragma unroll
            for (int j = 0; j < 8; ++j) o[i][j] *= al[i];
        }
        for (int kv = 0; kv < 64; ++kv) {
            float4 v0 = *(const float4*)(KVu + kv * 128 + c0p);
            float4 v1 = *(const float4*)(KVu + kv * 128 + c0p + 4);
#pragma unroll
            for (int i = 0; i < 4; ++i) {
                float p = Ss[(r0 + i) * SS_LD + kv];
                o[i][0] = fmaf(p, v0.x, o[i][0]);
                o[i][1] = fmaf(p, v0.y, o[i][1]);
                o[i][2] = fmaf(p, v0.z, o[i][2]);
                o[i][3] = fmaf(p, v0.w, o[i][3]);
                o[i][4] = fmaf(p, v1.x, o[i][4]);
                o[i][5] = fmaf(p, v1.y, o[i][5]);
                o[i][6] = fmaf(p, v1.z, o[i][6]);
                o[i][7] = fmaf(p, v1.w, o[i][7]);
            }
        }
        __syncthreads();
    }

#pragma unroll
    for (int i = 0; i < 4; ++i) {
        float inv = 1.0f / l_sm[r0 + i];
        float* dst = O + (size_t)(b * TT + q0 + r0 + i) * CC + h * DD + c0p;
        *(float4*)dst       = make_float4(o[i][0]*inv, o[i][1]*inv, o[i][2]*inv, o[i][3]*inv);
        *(float4*)(dst + 4) = make_float4(o[i][4]*inv, o[i][5]*inv, o[i][6]*inv, o[i][7]*inv);
    }
}

// ---------------------------------------------------------------------------
// Launch
// ---------------------------------------------------------------------------
extern "C" void kernel_launch(void* const* d_in, const int* in_sizes, int n_in,
                              void* d_out, int out_size)
{
    const float* x  = (const float*)d_in[0];
    const float* Wq = (const float*)d_in[1];
    const float* Wk = (const float*)d_in[2];
    const float* Wv = (const float*)d_in[3];
    const float* Wo = (const float*)d_in[4];
    float* out = (float*)d_out;

    float *q_ptr, *k_ptr, *v_ptr, *attn_ptr;
    cudaGetSymbolAddress((void**)&q_ptr,    g_q);
    cudaGetSymbolAddress((void**)&k_ptr,    g_k);
    cudaGetSymbolAddress((void**)&v_ptr,    g_v);
    cudaGetSymbolAddress((void**)&attn_ptr, g_attn);

    const int M = BB * TT;   // 4096

    // Projections (tf32 3-pass split tensor-core GEMM)
    tf32_gemm_kernel<<<dim3(CC / 128, M / 128), 256>>>(x, Wq, q_ptr, M, CC, CC);
    tf32_gemm_kernel<<<dim3((KVH * DD) / 128, M / 128), 256>>>(x, Wk, k_ptr, M, KVH * DD, CC);
    tf32_gemm_kernel<<<dim3((KVH * DD) / 128, M / 128), 256>>>(x, Wv, v_ptr, M, KVH * DD, CC);

    // RoPE on q and k
    {
        int pairs_q = BB * TT * HH * HALF;
        int pairs_k = BB * TT * KVH * HALF;
        rope_kernel<<<(pairs_q + 255) / 256, 256>>>(q_ptr, HH, pairs_q);
        rope_kernel<<<(pairs_k + 255) / 256, 256>>>(k_ptr, KVH, pairs_k);
    }

    // Attention
    cudaFuncSetAttribute(attn_kernel, cudaFuncAttributeMaxDynamicSharedMemorySize,
                         ATTN_SMEM_BYTES);
    attn_kernel<<<dim3(TT / 64, HH, BB), 256, ATTN_SMEM_BYTES>>>(q_ptr, k_ptr, v_ptr, attn_ptr);

    // Output projection
    tf32_gemm_kernel<<<dim3(CC / 128, M / 128), 256>>>(attn_ptr, Wo, out, M, CC, CC);
}

// round 13
// speedup vs baseline: 1.9104x; 1.9104x over previous
#include <cuda_runtime.h>
#include <cuda_bf16.h>
#include <math.h>
#include <stdint.h>

// Problem constants
#define BB 2
#define TT 2048
#define CC 2048
#define HH 16
#define KVH 4
#define DD 128
#define RR 4            // HH / KVH
#define HALF 64         // DD/2

// ---------------------------------------------------------------------------
// Scratch (device globals — allowed)
// ---------------------------------------------------------------------------
__device__ float g_q[(size_t)BB * TT * HH * DD];     // (B,T,H,D)
__device__ float g_k[(size_t)BB * TT * KVH * DD];    // (B,T,KV,D)
__device__ float g_v[(size_t)BB * TT * KVH * DD];    // (B,T,KV,D)
__device__ float g_attn[(size_t)BB * TT * CC];       // (B,T,C)

// ---------------------------------------------------------------------------
// Fast exp (FFMA-only). Valid for x <= ~0, handles -1e30 mask.
// ---------------------------------------------------------------------------
__device__ __forceinline__ float fast_exp(float x) {
    float t = x * 1.4426950408889634f;          // log2(e)
    if (t < -126.0f) return 0.0f;
    float z = t + 12582912.0f;                  // 1.5 * 2^23
    float fi = z - 12582912.0f;
    float f = t - fi;                           // f in [-0.5, 0.5]
    int e = __float_as_int(z) - 0x4B400000;
    float p = 1.535336188319500e-4f;
    p = fmaf(p, f, 1.339887440266574e-3f);
    p = fmaf(p, f, 9.618437357674640e-3f);
    p = fmaf(p, f, 5.550332471162809e-2f);
    p = fmaf(p, f, 2.402264791363012e-1f);
    p = fmaf(p, f, 6.931472028550421e-1f);
    p = fmaf(p, f, 1.0f);
    float scale = __int_as_float((e + 127) << 23);
    return p * scale;
}

// ---------------------------------------------------------------------------
// bf16 helpers
// ---------------------------------------------------------------------------
__device__ __forceinline__ void split_bf16(float v, __nv_bfloat16& h, __nv_bfloat16& l) {
    h = __float2bfloat16_rn(v);
    l = __float2bfloat16_rn(v - __bfloat162float(h));
}

__device__ __forceinline__ void mma_bf16(float* c, const uint32_t* a, const uint32_t* b) {
    asm volatile(
        "mma.sync.aligned.m16n8k16.row.col.f32.bf16.bf16.f32 "
        "{%0,%1,%2,%3}, {%4,%5,%6,%7}, {%8,%9}, {%0,%1,%2,%3};"
        : "+f"(c[0]), "+f"(c[1]), "+f"(c[2]), "+f"(c[3])
        : "r"(a[0]), "r"(a[1]), "r"(a[2]), "r"(a[3]), "r"(b[0]), "r"(b[1]));
}

// ---------------------------------------------------------------------------
// bf16 3-pass split GEMM: C = A(MxK) @ B(KxN), row-major, ~fp32 quality.
// BM=BN=128, BK=16, 256 threads = 8 warps (2x4), warp tile 64x32,
// per warp 4x4 mma tiles of m16n8k16 x 3 passes (hh, hl, lh).
// ---------------------------------------------------------------------------
__global__ void __launch_bounds__(256) bf16_gemm_kernel(
    const float* __restrict__ A, const float* __restrict__ B,
    float* __restrict__ C, int M, int N, int K)
{
    // rows padded to 24 bf16 (12 words): frag-load banks (12*m + t) distinct
    __shared__ __nv_bfloat16 Ah[128][24];
    __shared__ __nv_bfloat16 Al[128][24];
    __shared__ __nv_bfloat16 Bh[128][24];   // [n][k] layout
    __shared__ __nv_bfloat16 Bl[128][24];

    const int tid  = threadIdx.x;
    const int warp = tid >> 5;
    const int lane = tid & 31;
    const int g    = lane >> 2;     // 0..7
    const int t    = lane & 3;      // 0..3
    const int wm   = (warp >> 2) * 64;   // {0, 64}
    const int wn   = (warp & 3) * 32;    // {0,32,64,96}
    const int row0 = blockIdx.y * 128;
    const int col0 = blockIdx.x * 128;

    const int bn  = tid & 127;          // B loader: column
    const int bkb = (tid >> 7) * 8;     // B loader: k base {0,8}

    float acc[4][4][4];
#pragma unroll
    for (int i = 0; i < 4; ++i)
#pragma unroll
        for (int j = 0; j < 4; ++j)
#pragma unroll
            for (int c = 0; c < 4; ++c) acc[i][j][c] = 0.0f;

    for (int k0 = 0; k0 < K; k0 += 16) {
        // --- A tile (128x16), split to hi/lo bf16 ---
#pragma unroll
        for (int ld = 0; ld < 2; ++ld) {
            int idx = tid + ld * 256;            // 0..511
            int m  = idx >> 2;                   // 0..127
            int kq = (idx & 3) << 2;             // 0,4,8,12
            float4 v = *(const float4*)&A[(size_t)(row0 + m) * K + k0 + kq];
            __nv_bfloat162 h01, h23, l01, l23;
            split_bf16(v.x, h01.x, l01.x);
            split_bf16(v.y, h01.y, l01.y);
            split_bf16(v.z, h23.x, l23.x);
            split_bf16(v.w, h23.y, l23.y);
            *(__nv_bfloat162*)&Ah[m][kq]     = h01;
            *(__nv_bfloat162*)&Ah[m][kq + 2] = h23;
            *(__nv_bfloat162*)&Al[m][kq]     = l01;
            *(__nv_bfloat162*)&Al[m][kq + 2] = l23;
        }
        // --- B tile (16x128) -> smem [n][k], split ---
        {
            float bv[8];
#pragma unroll
            for (int kk = 0; kk < 8; ++kk)
                bv[kk] = B[(size_t)(k0 + bkb + kk) * N + col0 + bn];
#pragma unroll
            for (int p = 0; p < 4; ++p) {
                __nv_bfloat162 hp, lp;
                split_bf16(bv[2 * p],     hp.x, lp.x);
                split_bf16(bv[2 * p + 1], hp.y, lp.y);
                *(__nv_bfloat162*)&Bh[bn][bkb + 2 * p] = hp;
                *(__nv_bfloat162*)&Bl[bn][bkb + 2 * p] = lp;
            }
        }
        __syncthreads();

        // --- one k16 MMA step, 3 passes ---
        uint32_t bhf[4][2], blf[4][2];
#pragma unroll
        for (int nt = 0; nt < 4; ++nt) {
            int col = wn + nt * 8 + g;
            bhf[nt][0] = *(const uint32_t*)&Bh[col][2 * t];
            bhf[nt][1] = *(const uint32_t*)&Bh[col][2 * t + 8];
            blf[nt][0] = *(const uint32_t*)&Bl[col][2 * t];
            blf[nt][1] = *(const uint32_t*)&Bl[col][2 * t + 8];
        }
#pragma unroll
        for (int mt = 0; mt < 4; ++mt) {
            int rm = wm + mt * 16 + g;
            uint32_t ah[4], al[4];
            ah[0] = *(const uint32_t*)&Ah[rm][2 * t];
            ah[1] = *(const uint32_t*)&Ah[rm + 8][2 * t];
            ah[2] = *(const uint32_t*)&Ah[rm][2 * t + 8];
            ah[3] = *(const uint32_t*)&Ah[rm + 8][2 * t + 8];
            al[0] = *(const uint32_t*)&Al[rm][2 * t];
            al[1] = *(const uint32_t*)&Al[rm + 8][2 * t];
            al[2] = *(const uint32_t*)&Al[rm][2 * t + 8];
            al[3] = *(const uint32_t*)&Al[rm + 8][2 * t + 8];
#pragma unroll
            for (int nt = 0; nt < 4; ++nt) {
                mma_bf16(acc[mt][nt], ah, bhf[nt]);   // hi*hi
                mma_bf16(acc[mt][nt], ah, blf[nt]);   // hi*lo
                mma_bf16(acc[mt][nt], al, bhf[nt]);   // lo*hi
            }
        }
        __syncthreads();
    }

    // Epilogue: c0,c1 -> (row, 2t), (row, 2t+1); c2,c3 -> (row+8, ...)
#pragma unroll
    for (int mt = 0; mt < 4; ++mt) {
#pragma unroll
        for (int nt = 0; nt < 4; ++nt) {
            int row = row0 + wm + mt * 16 + g;
            int col = col0 + wn + nt * 8 + 2 * t;
            float2 v01 = make_float2(acc[mt][nt][0], acc[mt][nt][1]);
            float2 v23 = make_float2(acc[mt][nt][2], acc[mt][nt][3]);
            *(float2*)&C[(size_t)row * N + col]       = v01;
            *(float2*)&C[(size_t)(row + 8) * N + col] = v23;
        }
    }
}

// ---------------------------------------------------------------------------
// RoPE in-place over X: (B, T, NH, D). One thread per (b,t,h,freq) pair.
// ---------------------------------------------------------------------------
__global__ void rope_kernel(float* __restrict__ X, int NH, int total_pairs)
{
    int idx = blockIdx.x * blockDim.x + threadIdx.x;
    if (idx >= total_pairs) return;
    int i = idx & (HALF - 1);
    int h = (idx >> 6) % NH;
    int t = (idx / (HALF * NH)) % TT;
    int b = idx / (HALF * NH * TT);

    float theta = powf(10000.0f, -(float)i * (1.0f / (float)HALF));
    float ang = (float)t * theta;
    float s, c;
    sincosf(ang, &s, &c);

    size_t base = (((size_t)b * TT + t) * NH + h) * DD;
    float x1 = X[base + i];
    float x2 = X[base + i + HALF];
    X[base + i]        = x1 * c - x2 * s;
    X[base + i + HALF] = x2 * c + x1 * s;
}

// ---------------------------------------------------------------------------
// Flash attention, bf16 3-pass split MMA for S=QK^T and PV; fp32 smem softmax.
// BQ=BKV=64, D=128, 256 threads (8 warps). Q:(B,T,H,D) K,V:(B,T,KV,D)
// O:(B,T,C) with C index = h*D + d.  grid: (T/64, H, B), qtile reversed.
// ---------------------------------------------------------------------------
#define AT_QK_LD 136   // Q/K smem row length in bf16 (128 + 8 pad; 68 words)
#define AT_VP_LD 72    // Vt/P smem row length in bf16 (64 + 8 pad; 36 words)

// byte offsets into dynamic smem
#define ASM_QH 0
#define ASM_QL (ASM_QH + 64 * AT_QK_LD * 2)          // 17408
#define ASM_KV (ASM_QL + 64 * AT_QK_LD * 2)          // 34816 (union region, 36864 B)
#define ASM_SS (ASM_KV + 36864)                      // 71680
#define ASM_PH (ASM_SS + 64 * 65 * 4)                // 88320
#define ASM_PL (ASM_PH + 64 * AT_VP_LD * 2)          // 97536
#define ASM_ST (ASM_PL + 64 * AT_VP_LD * 2)          // 106752
#define ASM_TOTAL (ASM_ST + 3 * 64 * 4)              // 107520
#define ATTN_SMEM_BYTES ASM_TOTAL

__global__ void __launch_bounds__(256) attn_kernel(
    const float* __restrict__ Q, const float* __restrict__ K,
    const float* __restrict__ V, float* __restrict__ O)
{
    extern __shared__ char smem[];
    __nv_bfloat16* Qh  = (__nv_bfloat16*)(smem + ASM_QH);
    __nv_bfloat16* Ql  = (__nv_bfloat16*)(smem + ASM_QL);
    __nv_bfloat16* Kh  = (__nv_bfloat16*)(smem + ASM_KV);          // K phase
    __nv_bfloat16* Kl  = Kh + 64 * AT_QK_LD;
    __nv_bfloat16* Vth = (__nv_bfloat16*)(smem + ASM_KV);          // V phase (union)
    __nv_bfloat16* Vtl = Vth + 128 * AT_VP_LD;
    float* Ss   = (float*)(smem + ASM_SS);                         // [64][65]
    __nv_bfloat16* Ph = (__nv_bfloat16*)(smem + ASM_PH);
    __nv_bfloat16* Pl = (__nv_bfloat16*)(smem + ASM_PL);
    float* m_sm = (float*)(smem + ASM_ST);
    float* l_sm = m_sm + 64;
    float* a_sm = l_sm + 64;

    const int tid   = threadIdx.x;
    const int warp  = tid >> 5;
    const int lane  = tid & 31;
    const int g     = lane >> 2;
    const int t     = lane & 3;
    const int qtile = (int)gridDim.x - 1 - (int)blockIdx.x;   // big tiles first
    const int h     = blockIdx.y;
    const int b     = blockIdx.z;
    const int kvh   = h >> 2;            // GQA kv head
    const int q0    = qtile * 64;

    // --- load Q tile (64x128), split into Qh/Ql ---
    for (int i = tid; i < 64 * 32; i += 256) {       // 2048 float4s
        int r  = i >> 5;
        int dq = (i & 31) * 4;
        float4 v = *(const float4*)&Q[(size_t)(b * TT + q0 + r) * (HH * DD) + h * DD + dq];
        __nv_bfloat162 h01, h23, l01, l23;
        split_bf16(v.x, h01.x, l01.x);
        split_bf16(v.y, h01.y, l01.y);
        split_bf16(v.z, h23.x, l23.x);
        split_bf16(v.w, h23.y, l23.y);
        *(__nv_bfloat162*)(Qh + r * AT_QK_LD + dq)     = h01;
        *(__nv_bfloat162*)(Qh + r * AT_QK_LD + dq + 2) = h23;
        *(__nv_bfloat162*)(Ql + r * AT_QK_LD + dq)     = l01;
        *(__nv_bfloat162*)(Ql + r * AT_QK_LD + dq + 2) = l23;
    }
    if (tid < 64) { m_sm[tid] = -1e30f; l_sm[tid] = 0.0f; }

    // S warps: (wr 0..3)=m16-tile, (wc 0..1)=n32-block
    const int wr = warp & 3, wc = warp >> 2;
    // PV warps: (wr2 0..3)=m16-tile, (wc2 0..1)=n64-block
    const int wr2 = warp & 3, wc2 = warp >> 2;

    float accO[8][4];
#pragma unroll
    for (int i = 0; i < 8; ++i)
#pragma unroll
        for (int c = 0; c < 4; ++c) accO[i][c] = 0.0f;

    const float scale = 0.08838834764831843f;   // 1/sqrt(128)

    for (int tt = 0; tt <= qtile; ++tt) {
        const int s0 = tt * 64;
        __syncthreads();   // Q ready (first iter) / prior PV done with Vt

        // --- load K tile (64x128) [s][d], split ---
        for (int i = tid; i < 64 * 32; i += 256) {
            int r  = i >> 5;
            int dq = (i & 31) * 4;
            float4 v = *(const float4*)&K[(size_t)(b * TT + s0 + r) * (KVH * DD) + kvh * DD + dq];
            __nv_bfloat162 h01, h23, l01, l23;
            split_bf16(v.x, h01.x, l01.x);
            split_bf16(v.y, h01.y, l01.y);
            split_bf16(v.z, h23.x, l23.x);
            split_bf16(v.w, h23.y, l23.y);
            *(__nv_bfloat162*)(Kh + r * AT_QK_LD + dq)     = h01;
            *(__nv_bfloat162*)(Kh + r * AT_QK_LD + dq + 2) = h23;
            *(__nv_bfloat162*)(Kl + r * AT_QK_LD + dq)     = l01;
            *(__nv_bfloat162*)(Kl + r * AT_QK_LD + dq + 2) = l23;
        }
        __syncthreads();

        // --- S = Q @ K^T via bf16 3-pass MMA (M=64,N=64,K=128) ---
        float cS[4][4];
#pragma unroll
        for (int nt = 0; nt < 4; ++nt)
#pragma unroll
            for (int c = 0; c < 4; ++c) cS[nt][c] = 0.0f;

        const int arow = wr * 16 + g;
#pragma unroll
        for (int ks = 0; ks < 8; ++ks) {
            int aw = ks * 16 + 2 * t;
            uint32_t ah[4], al[4];
            ah[0] = *(const uint32_t*)(Qh + arow * AT_QK_LD + aw);
            ah[1] = *(const uint32_t*)(Qh + (arow + 8) * AT_QK_LD + aw);
            ah[2] = *(const uint32_t*)(Qh + arow * AT_QK_LD + aw + 8);
            ah[3] = *(const uint32_t*)(Qh + (arow + 8) * AT_QK_LD + aw + 8);
            al[0] = *(const uint32_t*)(Ql + arow * AT_QK_LD + aw);
            al[1] = *(const uint32_t*)(Ql + (arow + 8) * AT_QK_LD + aw);
            al[2] = *(const uint32_t*)(Ql + arow * AT_QK_LD + aw + 8);
            al[3] = *(const uint32_t*)(Ql + (arow + 8) * AT_QK_LD + aw + 8);
#pragma unroll
            for (int nt = 0; nt < 4; ++nt) {
                int bcol = wc * 32 + nt * 8 + g;
                uint32_t bh[2], bl[2];
                bh[0] = *(const uint32_t*)(Kh + bcol * AT_QK_LD + aw);
                bh[1] = *(const uint32_t*)(Kh + bcol * AT_QK_LD + aw + 8);
                bl[0] = *(const uint32_t*)(Kl + bcol * AT_QK_LD + aw);
                bl[1] = *(const uint32_t*)(Kl + bcol * AT_QK_LD + aw + 8);
                mma_bf16(cS[nt], ah, bh);
                mma_bf16(cS[nt], ah, bl);
                mma_bf16(cS[nt], al, bh);
            }
        }
        // epilogue: scale + causal mask (diagonal tile only) -> Ss
        const bool diag = (tt == qtile);
#pragma unroll
        for (int nt = 0; nt < 4; ++nt) {
            int col = wc * 32 + nt * 8 + 2 * t;
            float v0 = cS[nt][0] * scale;
            float v1 = cS[nt][1] * scale;
            float v2 = cS[nt][2] * scale;
            float v3 = cS[nt][3] * scale;
            if (diag) {
                if (col     > arow)     v0 = -1e30f;
                if (col + 1 > arow)     v1 = -1e30f;
                if (col     > arow + 8) v2 = -1e30f;
                if (col + 1 > arow + 8) v3 = -1e30f;
            }
            Ss[arow * 65 + col]           = v0;
            Ss[arow * 65 + col + 1]       = v1;
            Ss[(arow + 8) * 65 + col]     = v2;
            Ss[(arow + 8) * 65 + col + 1] = v3;
        }
        __syncthreads();

        // --- online softmax over Ss rows (unchanged smem path) ---
        for (int r = warp; r < 64; r += 8) {
            float v0 = Ss[r * 65 + lane];
            float v1 = Ss[r * 65 + lane + 32];
            float mx = fmaxf(v0, v1);
#pragma unroll
            for (int off = 16; off > 0; off >>= 1)
                mx = fmaxf(mx, __shfl_xor_sync(0xffffffffu, mx, off));
            float m_old = m_sm[r];
            float m_new = fmaxf(m_old, mx);
            float p0 = fast_exp(v0 - m_new);
            float p1 = fast_exp(v1 - m_new);
            Ss[r * 65 + lane]      = p0;
            Ss[r * 65 + lane + 32] = p1;
            float s = p0 + p1;
#pragma unroll
            for (int off = 16; off > 0; off >>= 1)
                s += __shfl_xor_sync(0xffffffffu, s, off);
            if (lane == 0) {
                float a = fast_exp(m_old - m_new);
                a_sm[r] = a;
                l_sm[r] = l_sm[r] * a + s;
                m_sm[r] = m_new;
            }
        }
        __syncthreads();

        // --- P -> bf16 split; V load + transpose + split (overwrites K region) ---
        for (int i = tid; i < 64 * 64; i += 256) {
            int r = i >> 6, c2 = i & 63;
            float p = Ss[r * 65 + c2];
            __nv_bfloat16 ph, pl;
            split_bf16(p, ph, pl);
            Ph[r * AT_VP_LD + c2] = ph;
            Pl[r * AT_VP_LD + c2] = pl;
        }
        for (int i = tid; i < 64 * 128; i += 256) {
            int s = i >> 7, d = i & 127;
            float v = V[(size_t)(b * TT + s0 + s) * (KVH * DD) + kvh * DD + d];
            __nv_bfloat16 vh, vl;
            split_bf16(v, vh, vl);
            Vth[d * AT_VP_LD + s] = vh;
            Vtl[d * AT_VP_LD + s] = vl;
        }
        __syncthreads();

        // --- O = O*alpha + P @ V via bf16 3-pass MMA (M=64,N=128,K=64) ---
        const int prow = wr2 * 16 + g;
        float alpha0 = a_sm[prow];
        float alpha1 = a_sm[prow + 8];
#pragma unroll
        for (int nt = 0; nt < 8; ++nt) {
            accO[nt][0] *= alpha0;
            accO[nt][1] *= alpha0;
            accO[nt][2] *= alpha1;
            accO[nt][3] *= alpha1;
        }
#pragma unroll
        for (int ks = 0; ks < 4; ++ks) {
            int aw = ks * 16 + 2 * t;
            uint32_t ah[4], al[4];
            ah[0] = *(const uint32_t*)(Ph + prow * AT_VP_LD + aw);
            ah[1] = *(const uint32_t*)(Ph + (prow + 8) * AT_VP_LD + aw);
            ah[2] = *(const uint32_t*)(Ph + prow * AT_VP_LD + aw + 8);
            ah[3] = *(const uint32_t*)(Ph + (prow + 8) * AT_VP_LD + aw + 8);
            al[0] = *(const uint32_t*)(Pl + prow * AT_VP_LD + aw);
            al[1] = *(const uint32_t*)(Pl + (prow + 8) * AT_VP_LD + aw);
            al[2] = *(const uint32_t*)(Pl + prow * AT_VP_LD + aw + 8);
            al[3] = *(const uint32_t*)(Pl + (prow + 8) * AT_VP_LD + aw + 8);
#pragma unroll
            for (int nt = 0; nt < 8; ++nt) {
                int vrow = wc2 * 64 + nt * 8 + g;    // d index
                uint32_t bh[2], bl[2];
                bh[0] = *(const uint32_t*)(Vth + vrow * AT_VP_LD + aw);
                bh[1] = *(const uint32_t*)(Vth + vrow * AT_VP_LD + aw + 8);
                bl[0] = *(const uint32_t*)(Vtl + vrow * AT_VP_LD + aw);
                bl[1] = *(const uint32_t*)(Vtl + vrow * AT_VP_LD + aw + 8);
                mma_bf16(accO[nt], ah, bh);
                mma_bf16(accO[nt], ah, bl);
                mma_bf16(accO[nt], al, bh);
            }
        }
    }

    // --- finalize: divide by l, write (B,T,C) ---
    const int orow = wr2 * 16 + g;
    float inv0 = 1.0f / l_sm[orow];
    float inv1 = 1.0f / l_sm[orow + 8];
#pragma unroll
    for (int nt = 0; nt < 8; ++nt) {
        int col = wc2 * 64 + nt * 8 + 2 * t;
        float2 lo = make_float2(accO[nt][0] * inv0, accO[nt][1] * inv0);
        float2 hi = make_float2(accO[nt][2] * inv1, accO[nt][3] * inv1);
        *(float2*)&O[(size_t)(b * TT + q0 + orow) * CC + h * DD + col]     = lo;
        *(float2*)&O[(size_t)(b * TT + q0 + orow + 8) * CC + h * DD + col] = hi;
    }
}

// ---------------------------------------------------------------------------
// Launch
// ---------------------------------------------------------------------------
extern "C" void kernel_launch(void* const* d_in, const int* in_sizes, int n_in,
                              void* d_out, int out_size)
{
    const float* x  = (const float*)d_in[0];
    const float* Wq = (const float*)d_in[1];
    const float* Wk = (const float*)d_in[2];
    const float* Wv = (const float*)d_in[3];
    const float* Wo = (const float*)d_in[4];
    float* out = (float*)d_out;

    float *q_ptr, *k_ptr, *v_ptr, *attn_ptr;
    cudaGetSymbolAddress((void**)&q_ptr,    g_q);
    cudaGetSymbolAddress((void**)&k_ptr,    g_k);
    cudaGetSymbolAddress((void**)&v_ptr,    g_v);
    cudaGetSymbolAddress((void**)&attn_ptr, g_attn);

    const int M = BB * TT;   // 4096

    // Projections (bf16 3-pass split tensor-core GEMM)
    bf16_gemm_kernel<<<dim3(CC / 128, M / 128), 256>>>(x, Wq, q_ptr, M, CC, CC);
    bf16_gemm_kernel<<<dim3((KVH * DD) / 128, M / 128), 256>>>(x, Wk, k_ptr, M, KVH * DD, CC);
    bf16_gemm_kernel<<<dim3((KVH * DD) / 128, M / 128), 256>>>(x, Wv, v_ptr, M, KVH * DD, CC);

    // RoPE on q and k
    {
        int pairs_q = BB * TT * HH * HALF;
        int pairs_k = BB * TT * KVH * HALF;
        rope_kernel<<<(pairs_q + 255) / 256, 256>>>(q_ptr, HH, pairs_q);
        rope_kernel<<<(pairs_k + 255) / 256, 256>>>(k_ptr, KVH, pairs_k);
    }

    // Attention (bf16 split MMA)
    cudaFuncSetAttribute(attn_kernel, cudaFuncAttributeMaxDynamicSharedMemorySize,
                         ATTN_SMEM_BYTES);
    attn_kernel<<<dim3(TT / 64, HH, BB), 256, ATTN_SMEM_BYTES>>>(q_ptr, k_ptr, v_ptr, attn_ptr);

    // Output projection
    bf16_gemm_kernel<<<dim3(CC / 128, M / 128), 256>>>(attn_ptr, Wo, out, M, CC, CC);
}